// round 3
// baseline (speedup 1.0000x reference)
#include <cuda_runtime.h>
#include <cstdint>

#define NB    16384
#define NSTEP 100
#define DTC   0.1f
#define CH    8
#define SPAD  68                      // staging stride: conflict-free STS + flush LDS
#define OUT_WORDS (22 * CH * SPAD)    // 11968
#define MEAS_OFF  OUT_WORDS
#define MEAS_BUF  (2 * 64 * 12)       // 1536 words per buffer
#define CTRL_OFF  (MEAS_OFF + 2 * MEAS_BUF)
#define CTRL_BUF  (64 * 20)           // 1280 words per buffer
#define SMEM_WORDS (CTRL_OFF + 2 * CTRL_BUF)
#define SMEM_BYTES (SMEM_WORDS * 4)   // 70400 B

__device__ __forceinline__ void cp16(uint32_t dst, const float* src) {
    asm volatile("cp.async.ca.shared.global [%0], [%1], 16;\n" :: "r"(dst), "l"(src));
}

// cooperative, sector-packed input prefetch for one 8-step chunk
__device__ __forceinline__ void issue_inputs(
    uint32_t smem_u32, const float* __restrict__ meas, const float* __restrict__ ctrl,
    int b0, int tid, int buf, int s0, bool full)
{
#pragma unroll
    for (int k = 0; k < 4; k++) {                  // meas: 2 m * 64 f * 2 halves
        int id = tid + 64 * k;
        int half = id & 1, f = (id >> 1) & 63, m = id >> 7;
        if (full || half == 0)
            cp16(smem_u32 + (uint32_t)(MEAS_OFF + buf * MEAS_BUF + (m * 64 + f) * 12 + half * 4) * 4,
                 meas + (size_t)(b0 + f) * 200 + m * 100 + s0 + 4 * half);
    }
#pragma unroll
    for (int k = 0; k < 4; k++) {                  // ctrl: 64 f * 4 quarters
        int id = tid + 64 * k;
        int q = id & 3, f = id >> 2;
        if (full || q < 2)
            cp16(smem_u32 + (uint32_t)(CTRL_OFF + buf * CTRL_BUF + f * 20 + q * 4) * 4,
                 ctrl + (size_t)(b0 + f) * 200 + 2 * s0 + 4 * q);
    }
    asm volatile("cp.async.commit_group;\n");
}

__device__ __forceinline__ void flush_chunk(
    const float* __restrict__ sm, float* __restrict__ preds, float* __restrict__ states,
    float* __restrict__ covs, int blk, int tid, int s0)
{
    const int h  = tid & 1;
    const int f0 = tid >> 1;
#pragma unroll
    for (int p = 0; p < 2; p++) {
        const int f  = f0 + 32 * p;
        const int gb = blk * 64 + f;
        float* pp = preds  + (size_t)gb * 200  + s0 + 4 * h;
        float* ps = states + (size_t)gb * 400  + s0 + 4 * h;
        float* pc = covs   + (size_t)gb * 1600 + s0 + 4 * h;
#pragma unroll
        for (int r = 0; r < 22; r++) {
            const float* s_ = sm + (r * CH + 4 * h) * SPAD + f;
            float4 v = make_float4(s_[0], s_[SPAD], s_[2 * SPAD], s_[3 * SPAD]);
            float* dst = (r < 2) ? (pp + r * 100)
                       : (r < 6) ? (ps + (r - 2) * 100)
                                 : (pc + (r - 6) * 100);
            *reinterpret_cast<float4*>(dst) = v;
        }
    }
}

__global__ __launch_bounds__(64) void ukf_kernel(
    const float* __restrict__ meas,    // [B,2,100]
    const float* __restrict__ state0,  // [B,4]
    const float* __restrict__ cov0,    // [B,4,4]
    const float* __restrict__ ctrl,    // [B,100,2]
    const float* __restrict__ Qm,      // [4,4]
    const float* __restrict__ Rm,      // [2,2]
    float* __restrict__ preds, float* __restrict__ states, float* __restrict__ covs)
{
    extern __shared__ float sm[];
    const uint32_t smem_u32 = (uint32_t)__cvta_generic_to_shared(sm);
    const int tid = threadIdx.x;
    const int b0  = blockIdx.x * 64;
    const int b   = b0 + tid;

    // ---- per-filter state: mean + upper-triangle covariance ----
    float x0, x1, x2, x3;
    {
        float4 xv = *reinterpret_cast<const float4*>(state0 + (size_t)b * 4);
        x0 = xv.x; x1 = xv.y; x2 = xv.z; x3 = xv.w;
    }
    float p00, p01, p02, p03, p11, p12, p13, p22, p23, p33;
    {
        const float4* pv = reinterpret_cast<const float4*>(cov0 + (size_t)b * 16);
        float4 r0 = pv[0], r1 = pv[1], r2 = pv[2], r3 = pv[3];
        p00 = r0.x; p01 = r0.y; p02 = r0.z; p03 = r0.w;
        p11 = r1.y; p12 = r1.z; p13 = r1.w;
        p22 = r2.z; p23 = r2.w;
        p33 = r3.w;
    }
    const float q00 = Qm[0],  q01 = Qm[1],  q02 = Qm[2],  q03 = Qm[3];
    const float q11 = Qm[5],  q12 = Qm[6],  q13 = Qm[7];
    const float q22 = Qm[10], q23 = Qm[11], q33 = Qm[15];
    const float r00 = Rm[0], r01 = Rm[1], r11 = Rm[3];

    // ---- preload chunk 0 ----
    issue_inputs(smem_u32, meas, ctrl, b0, tid, 0, 0, true);
    asm volatile("cp.async.wait_group 0;\n");
    __syncthreads();

#pragma unroll 1
    for (int ch = 0; ch < 13; ch++) {
        const int cur = ch & 1;
        const int nsteps = (ch < 12) ? CH : 4;

        if (ch < 12)  // prefetch next chunk (chunk 12 is the 4-step tail)
            issue_inputs(smem_u32, meas, ctrl, b0, tid, cur ^ 1, (ch + 1) * CH, (ch + 1) < 12);

        const float* ms0 = sm + MEAS_OFF + cur * MEAS_BUF + tid * 12;
        const float* ms1 = ms0 + 768;
        const float* cs  = sm + CTRL_OFF + cur * CTRL_BUF + tid * 20;

#pragma unroll
        for (int sp = 0; sp < CH; sp++) {
            if (sp >= nsteps) break;
            const float z0 = ms0[sp];
            const float z1 = ms1[sp];
            const float ux = cs[2 * sp];
            const float uy = cs[2 * sp + 1];

            // predict mean (exact affine collapse of sigma mean)
            const float xp0 = x0 + DTC * x2 + 0.5f * DTC * DTC * ux;
            const float xp1 = x1 + DTC * x3 + 0.5f * DTC * DTC * uy;
            const float xp2 = x2 + DTC * ux;
            const float xp3 = x3 + DTC * uy;

            // A = M P M^T (symmetric, == weighted sigma outer-product sum exactly)
            const float a02 = p02 + DTC * p22;
            const float a03 = p03 + DTC * p23;
            const float a12 = p12 + DTC * p23;
            const float a13 = p13 + DTC * p33;
            const float a00 = p00 + DTC * p02 + DTC * a02;
            const float a11 = p11 + DTC * p13 + DTC * a13;
            const float a01 = p01 + DTC * p03 + DTC * a12;
            const float a22 = p22, a23 = p23, a33 = p33;

            // S = A[:2,:2] + R ; 2x2 inverse
            const float s00 = a00 + r00;
            const float s01 = a01 + r01;
            const float s11 = a11 + r11;
            const float idet = 1.0f / (s00 * s11 - s01 * s01);
            const float i00 =  s11 * idet;
            const float i01 = -s01 * idet;
            const float i11 =  s00 * idet;

            // K = A[:, :2] * S^{-1}
            const float K00 = a00 * i00 + a01 * i01, K01 = a00 * i01 + a01 * i11;
            const float K10 = a01 * i00 + a11 * i01, K11 = a01 * i01 + a11 * i11;
            const float K20 = a02 * i00 + a12 * i01, K21 = a02 * i01 + a12 * i11;
            const float K30 = a03 * i00 + a13 * i01, K31 = a03 * i01 + a13 * i11;

            const float in0 = z0 - xp0, in1 = z1 - xp1;
            const float xn0 = xp0 + K00 * in0 + K01 * in1;
            const float xn1 = xp1 + K10 * in0 + K11 * in1;
            const float xn2 = xp2 + K20 * in0 + K21 * in1;
            const float xn3 = xp3 + K30 * in0 + K31 * in1;

            // P_new = A + Q - K S K^T (upper triangle)
            const float KS00 = K00 * s00 + K01 * s01, KS01 = K00 * s01 + K01 * s11;
            const float KS10 = K10 * s00 + K11 * s01, KS11 = K10 * s01 + K11 * s11;
            const float KS20 = K20 * s00 + K21 * s01, KS21 = K20 * s01 + K21 * s11;
            const float KS30 = K30 * s00 + K31 * s01, KS31 = K30 * s01 + K31 * s11;
            p00 = a00 + q00 - (KS00 * K00 + KS01 * K01);
            p01 = a01 + q01 - (KS00 * K10 + KS01 * K11);
            p02 = a02 + q02 - (KS00 * K20 + KS01 * K21);
            p03 = a03 + q03 - (KS00 * K30 + KS01 * K31);
            p11 = a11 + q11 - (KS10 * K10 + KS11 * K11);
            p12 = a12 + q12 - (KS10 * K20 + KS11 * K21);
            p13 = a13 + q13 - (KS10 * K30 + KS11 * K31);
            p22 = a22 + q22 - (KS20 * K20 + KS21 * K21);
            p23 = a23 + q23 - (KS20 * K30 + KS21 * K31);
            p33 = a33 + q33 - (KS30 * K30 + KS31 * K31);
            x0 = xn0; x1 = xn1; x2 = xn2; x3 = xn3;

            // stage 22 outputs (conflict-free STS)
            float* st_ = sm + sp * SPAD + tid;
            st_[(0)  * CH * SPAD] = xp0;
            st_[(1)  * CH * SPAD] = xp1;
            st_[(2)  * CH * SPAD] = xn0;
            st_[(3)  * CH * SPAD] = xn1;
            st_[(4)  * CH * SPAD] = xn2;
            st_[(5)  * CH * SPAD] = xn3;
            st_[(6)  * CH * SPAD] = p00;
            st_[(7)  * CH * SPAD] = p01;
            st_[(8)  * CH * SPAD] = p02;
            st_[(9)  * CH * SPAD] = p03;
            st_[(10) * CH * SPAD] = p01;
            st_[(11) * CH * SPAD] = p11;
            st_[(12) * CH * SPAD] = p12;
            st_[(13) * CH * SPAD] = p13;
            st_[(14) * CH * SPAD] = p02;
            st_[(15) * CH * SPAD] = p12;
            st_[(16) * CH * SPAD] = p22;
            st_[(17) * CH * SPAD] = p23;
            st_[(18) * CH * SPAD] = p03;
            st_[(19) * CH * SPAD] = p13;
            st_[(20) * CH * SPAD] = p23;
            st_[(21) * CH * SPAD] = p33;
        }

        __syncthreads();   // staging complete

        if (ch < 12) {
            flush_chunk(sm, preds, states, covs, blockIdx.x, tid, ch * CH);
        } else {
            // tail: 4 steps at s0=96, one float4 per row per filter
            const int gb = blockIdx.x * 64 + tid;
            float* pp = preds  + (size_t)gb * 200  + 96;
            float* ps = states + (size_t)gb * 400  + 96;
            float* pc = covs   + (size_t)gb * 1600 + 96;
#pragma unroll
            for (int r = 0; r < 22; r++) {
                const float* s_ = sm + (r * CH) * SPAD + tid;
                float4 v = make_float4(s_[0], s_[SPAD], s_[2 * SPAD], s_[3 * SPAD]);
                float* dst = (r < 2) ? (pp + r * 100)
                           : (r < 6) ? (ps + (r - 2) * 100)
                                     : (pc + (r - 6) * 100);
                *reinterpret_cast<float4*>(dst) = v;
            }
        }

        asm volatile("cp.async.wait_group 0;\n");
        __syncthreads();   // inputs ready; staging buffer reusable
    }
}

extern "C" void kernel_launch(void* const* d_in, const int* in_sizes, int n_in,
                              void* d_out, int out_size)
{
    const float* meas  = (const float*)d_in[0];
    const float* state = (const float*)d_in[1];
    const float* cov   = (const float*)d_in[2];
    const float* ctrl  = (const float*)d_in[3];
    const float* Q     = (const float*)d_in[4];
    const float* R     = (const float*)d_in[5];

    float* out    = (float*)d_out;
    float* preds  = out;                              // 16384*2*100
    float* states = preds  + (size_t)NB * 2 * NSTEP;  // 16384*4*100
    float* covs   = states + (size_t)NB * 4 * NSTEP;  // 16384*16*100

    static int smem_set = 0;
    if (!smem_set) {
        cudaFuncSetAttribute(ukf_kernel,
                             cudaFuncAttributeMaxDynamicSharedMemorySize, SMEM_BYTES);
        smem_set = 1;
    }

    ukf_kernel<<<NB / 64, 64, SMEM_BYTES>>>(meas, state, cov, ctrl, Q, R,
                                            preds, states, covs);
}